// round 2
// baseline (speedup 1.0000x reference)
#include <cuda_runtime.h>
#include <cuda_bf16.h>

#define D_MODEL 1024
#define D_PROJ  256
#define BATCH   4
#define SEQ     2048

// Scratch for h = relu(hs @ W^T + b): [4, 2048, 256] fp32 (32 MiB)
__device__ float g_h[BATCH * SEQ * D_PROJ];

// ---------------------------------------------------------------------------
// GEMM 1: h[m, n] = relu( sum_k hs[m, k] * W[n, k] + bias[n] )
// M = 8192 (batch*seq flattened), N = 256, K = 1024. Both operands K-major (NT).
// 64x64 tile, BK=16, 256 threads, 4x4 register blocking.
// ---------------------------------------------------------------------------
__global__ __launch_bounds__(256) void proj_relu_kernel(
    const float* __restrict__ hs,
    const float* __restrict__ W,
    const float* __restrict__ bias)
{
    __shared__ float As[16][65];   // [k][m] transposed, pad to avoid conflicts
    __shared__ float Bs[16][65];   // [k][n]

    const int tid  = threadIdx.x;
    const int ty   = tid >> 4;     // 0..15
    const int tx   = tid & 15;     // 0..15
    const int row0 = blockIdx.y * 64;
    const int col0 = blockIdx.x * 64;

    const int lr  = tid >> 2;        // 0..63 load row
    const int lc4 = (tid & 3) * 4;   // 0,4,8,12 load col (k offset)

    float acc[4][4];
#pragma unroll
    for (int i = 0; i < 4; ++i)
#pragma unroll
        for (int j = 0; j < 4; ++j) acc[i][j] = 0.f;

    for (int k0 = 0; k0 < D_MODEL; k0 += 16) {
        // Load 64x16 A tile and 64x16 B tile, transposed into smem
        float4 va = *reinterpret_cast<const float4*>(
            &hs[(size_t)(row0 + lr) * D_MODEL + k0 + lc4]);
        As[lc4 + 0][lr] = va.x;
        As[lc4 + 1][lr] = va.y;
        As[lc4 + 2][lr] = va.z;
        As[lc4 + 3][lr] = va.w;

        float4 vb = *reinterpret_cast<const float4*>(
            &W[(size_t)(col0 + lr) * D_MODEL + k0 + lc4]);
        Bs[lc4 + 0][lr] = vb.x;
        Bs[lc4 + 1][lr] = vb.y;
        Bs[lc4 + 2][lr] = vb.z;
        Bs[lc4 + 3][lr] = vb.w;

        __syncthreads();

#pragma unroll
        for (int k = 0; k < 16; ++k) {
            float a[4], b[4];
#pragma unroll
            for (int i = 0; i < 4; ++i) a[i] = As[k][ty * 4 + i];
#pragma unroll
            for (int j = 0; j < 4; ++j) b[j] = Bs[k][tx * 4 + j];
#pragma unroll
            for (int i = 0; i < 4; ++i)
#pragma unroll
                for (int j = 0; j < 4; ++j)
                    acc[i][j] = fmaf(a[i], b[j], acc[i][j]);
        }
        __syncthreads();
    }

    // Epilogue: bias + relu, store to g_h
#pragma unroll
    for (int j = 0; j < 4; ++j) {
        const int col = col0 + tx * 4 + j;
        const float bv = bias[col];
#pragma unroll
        for (int i = 0; i < 4; ++i) {
            const int row = row0 + ty * 4 + i;
            float v = acc[i][j] + bv;
            g_h[(size_t)row * D_PROJ + col] = v > 0.f ? v : 0.f;
        }
    }
}

// ---------------------------------------------------------------------------
// GEMM 2: scores[b, i, j] = ( sum_p h[b,i,p] * h[b,j,p] ) * clf_w + clf_b
// Per batch: M = N = 2048, K = 256, both operands the same K-major matrix.
// ---------------------------------------------------------------------------
__global__ __launch_bounds__(256) void scores_kernel(
    const float* __restrict__ clf_w,
    const float* __restrict__ clf_b,
    float* __restrict__ out)
{
    __shared__ float As[16][65];
    __shared__ float Bs[16][65];

    const int tid  = threadIdx.x;
    const int ty   = tid >> 4;
    const int tx   = tid & 15;
    const int row0 = blockIdx.y * 64;
    const int col0 = blockIdx.x * 64;
    const int b    = blockIdx.z;

    const float* __restrict__ hb = g_h + (size_t)b * SEQ * D_PROJ;

    const int lr  = tid >> 2;
    const int lc4 = (tid & 3) * 4;

    float acc[4][4];
#pragma unroll
    for (int i = 0; i < 4; ++i)
#pragma unroll
        for (int j = 0; j < 4; ++j) acc[i][j] = 0.f;

    for (int k0 = 0; k0 < D_PROJ; k0 += 16) {
        float4 va = *reinterpret_cast<const float4*>(
            &hb[(size_t)(row0 + lr) * D_PROJ + k0 + lc4]);
        As[lc4 + 0][lr] = va.x;
        As[lc4 + 1][lr] = va.y;
        As[lc4 + 2][lr] = va.z;
        As[lc4 + 3][lr] = va.w;

        float4 vb = *reinterpret_cast<const float4*>(
            &hb[(size_t)(col0 + lr) * D_PROJ + k0 + lc4]);
        Bs[lc4 + 0][lr] = vb.x;
        Bs[lc4 + 1][lr] = vb.y;
        Bs[lc4 + 2][lr] = vb.z;
        Bs[lc4 + 3][lr] = vb.w;

        __syncthreads();

#pragma unroll
        for (int k = 0; k < 16; ++k) {
            float a[4], bb[4];
#pragma unroll
            for (int i = 0; i < 4; ++i) a[i] = As[k][ty * 4 + i];
#pragma unroll
            for (int j = 0; j < 4; ++j) bb[j] = Bs[k][tx * 4 + j];
#pragma unroll
            for (int i = 0; i < 4; ++i)
#pragma unroll
                for (int j = 0; j < 4; ++j)
                    acc[i][j] = fmaf(a[i], bb[j], acc[i][j]);
        }
        __syncthreads();
    }

    const float cw = __ldg(clf_w);
    const float cb = __ldg(clf_b);

    float* __restrict__ ob = out + (size_t)b * SEQ * SEQ;
#pragma unroll
    for (int i = 0; i < 4; ++i) {
        const int row = row0 + ty * 4 + i;
#pragma unroll
        for (int j = 0; j < 4; ++j) {
            const int col = col0 + tx * 4 + j;
            ob[(size_t)row * SEQ + col] = acc[i][j] * cw + cb;
        }
    }
}

extern "C" void kernel_launch(void* const* d_in, const int* in_sizes, int n_in,
                              void* d_out, int out_size)
{
    const float* hs     = (const float*)d_in[0];  // [4, 2048, 1024]
    const float* proj_w = (const float*)d_in[1];  // [256, 1024]
    const float* proj_b = (const float*)d_in[2];  // [256]
    const float* clf_w  = (const float*)d_in[3];  // [1, 1]
    const float* clf_b  = (const float*)d_in[4];  // [1]
    float* out = (float*)d_out;                   // [4, 2048, 2048]

    // GEMM 1: M = 8192 rows, N = 256 cols
    {
        dim3 grid(D_PROJ / 64, (BATCH * SEQ) / 64);  // (4, 128)
        proj_relu_kernel<<<grid, 256>>>(hs, proj_w, proj_b);
    }
    // GEMM 2: per batch 2048x2048
    {
        dim3 grid(SEQ / 64, SEQ / 64, BATCH);        // (32, 32, 4)
        scores_kernel<<<grid, 256>>>(clf_w, clf_b, out);
    }
}

// round 5
// speedup vs baseline: 2.1420x; 2.1420x over previous
#include <cuda_runtime.h>
#include <cuda_bf16.h>
#include <cstdint>

#define BATCH 4
#define SEQ   2048

// Split operand storage: [rows, 2K] bf16, cols [0,K) = hi, [K,2K) = lo
__device__ __nv_bfloat16 g_hs2[(size_t)8192 * 2048];  // 32 MiB
__device__ __nv_bfloat16 g_w2 [(size_t)256  * 2048];  // 1 MiB
__device__ __nv_bfloat16 g_h2 [(size_t)8192 * 512];   // 8 MiB (h split, K=256)

// ---------------------------------------------------------------------------
// PTX helpers (all plain sm_80-era instructions — valid at compute_103)
// ---------------------------------------------------------------------------
__device__ __forceinline__ unsigned smem_u32(const void* p) {
    unsigned a;
    asm("{ .reg .u64 t; cvta.to.shared.u64 t, %1; cvt.u32.u64 %0, t; }"
        : "=r"(a) : "l"(p));
    return a;
}

#define CP_ASYNC16(dst, src) \
    asm volatile("cp.async.cg.shared.global [%0], [%1], 16;" :: "r"(dst), "l"(src))
#define CP_COMMIT() asm volatile("cp.async.commit_group;" ::: "memory")
#define CP_WAIT1()  asm volatile("cp.async.wait_group 1;" ::: "memory")
#define CP_WAIT0()  asm volatile("cp.async.wait_group 0;" ::: "memory")

#define LDSM_X4(r0, r1, r2, r3, a) \
    asm volatile("ldmatrix.sync.aligned.m8n8.x4.shared.b16 {%0,%1,%2,%3}, [%4];" \
                 : "=r"(r0), "=r"(r1), "=r"(r2), "=r"(r3) : "r"(a))

#define MMA16816(d, a, b0, b1) \
    asm volatile( \
        "mma.sync.aligned.m16n8k16.row.col.f32.bf16.bf16.f32 " \
        "{%0,%1,%2,%3},{%4,%5,%6,%7},{%8,%9},{%0,%1,%2,%3};" \
        : "+f"((d)[0]), "+f"((d)[1]), "+f"((d)[2]), "+f"((d)[3]) \
        : "r"((a)[0]), "r"((a)[1]), "r"((a)[2]), "r"((a)[3]), "r"(b0), "r"(b1))

// Smem: stage0 A @0, stage0 B @16K, stage1 A @32K, stage1 B @48K
#define SMEM_BYTES 65536

// ---------------------------------------------------------------------------
// Split fp32 -> (hi, lo) bf16, layout [R, 2C]: hi cols [0,C), lo cols [C,2C)
// ---------------------------------------------------------------------------
__global__ __launch_bounds__(256) void split_kernel(const float* __restrict__ src,
                                                    int which, int C, int n4) {
    int i = blockIdx.x * blockDim.x + threadIdx.x;
    if (i >= n4) return;
    __nv_bfloat16* __restrict__ dst = which ? g_w2 : g_hs2;
    int e0 = i * 4;
    int r = e0 / C, c = e0 - r * C;
    float4 v = *reinterpret_cast<const float4*>(src + e0);

    __nv_bfloat16 h0 = __float2bfloat16(v.x), h1 = __float2bfloat16(v.y);
    __nv_bfloat16 h2 = __float2bfloat16(v.z), h3 = __float2bfloat16(v.w);
    __nv_bfloat16 l0 = __float2bfloat16(v.x - __bfloat162float(h0));
    __nv_bfloat16 l1 = __float2bfloat16(v.y - __bfloat162float(h1));
    __nv_bfloat16 l2 = __float2bfloat16(v.z - __bfloat162float(h2));
    __nv_bfloat16 l3 = __float2bfloat16(v.w - __bfloat162float(h3));

    __nv_bfloat16* rowp = dst + (size_t)r * (2 * C);
    *reinterpret_cast<__nv_bfloat162*>(rowp + c)         = __halves2bfloat162(h0, h1);
    *reinterpret_cast<__nv_bfloat162*>(rowp + c + 2)     = __halves2bfloat162(h2, h3);
    *reinterpret_cast<__nv_bfloat162*>(rowp + C + c)     = __halves2bfloat162(l0, l1);
    *reinterpret_cast<__nv_bfloat162*>(rowp + C + c + 2) = __halves2bfloat162(l2, l3);
}

// ---------------------------------------------------------------------------
// 3-term split K-chunk column mapping over [R, 2K] storage.
//   term0 (kk in [0,K)):    ahi * bhi  -> a col kk,      b col kk
//   term1 (kk in [K,2K)):   alo * bhi  -> a col kk (lo), b col kk-K
//   term2 (kk in [2K,3K)):  ahi * blo  -> a col kk-2K,   b col kk-K (lo)
// ---------------------------------------------------------------------------
__device__ __forceinline__ int acol_of(int c, int K) {
    int kk = c * 64; return kk < 2 * K ? kk : kk - 2 * K;
}
__device__ __forceinline__ int bcol_of(int c, int K) {
    int kk = c * 64; return kk < K ? kk : kk - K;
}

// Load one 128x64-bf16 chunk per operand into a smem stage (SW128-xor layout)
__device__ __forceinline__ void load_chunk(
    const __nv_bfloat16* __restrict__ Abase, const __nv_bfloat16* __restrict__ Bbase,
    int ld, int ac, int bc, unsigned sA, unsigned sB, int t)
{
#pragma unroll
    for (int i = 0; i < 4; ++i) {
        int idx = t + i * 256;          // 0..1023: 128 rows x 8 16B-chunks
        int row = idx >> 3, ch = idx & 7;
        unsigned dst = (unsigned)(row * 128 + ((ch ^ (row & 7)) << 4));
        const void* srcA = Abase + (size_t)row * ld + ac + ch * 8;
        const void* srcB = Bbase + (size_t)row * ld + bc + ch * 8;
        CP_ASYNC16(sA + dst, srcA);
        CP_ASYNC16(sB + dst, srcB);
    }
}

// Compute 4 k16-steps from one smem stage. Warp tile 32(M) x 64(N).
__device__ __forceinline__ void compute_stage(
    unsigned sA, unsigned sB, int lane, int wm, int wn, float (*acc)[8][4])
{
#pragma unroll
    for (int s = 0; s < 4; ++s) {
        const int ch = s * 2 + (lane >> 4);
        unsigned a[2][4], rb[4][4];
#pragma unroll
        for (int mi = 0; mi < 2; ++mi) {
            int row = wm * 32 + mi * 16 + (lane & 15);
            unsigned addr = sA + row * 128 + ((ch ^ (row & 7)) << 4);
            LDSM_X4(a[mi][0], a[mi][1], a[mi][2], a[mi][3], addr);
        }
#pragma unroll
        for (int p = 0; p < 4; ++p) {
            int row = wn * 64 + p * 16 + (lane & 15);
            unsigned addr = sB + row * 128 + ((ch ^ (row & 7)) << 4);
            LDSM_X4(rb[p][0], rb[p][1], rb[p][2], rb[p][3], addr);
        }
#pragma unroll
        for (int mi = 0; mi < 2; ++mi)
#pragma unroll
            for (int p = 0; p < 4; ++p) {
                MMA16816(acc[mi][2 * p],     a[mi], rb[p][0], rb[p][2]);
                MMA16816(acc[mi][2 * p + 1], a[mi], rb[p][1], rb[p][3]);
            }
    }
}

// Full mainloop: 2-stage cp.async pipeline over nchunks K-chunks.
__device__ __forceinline__ void gemm_main(
    const __nv_bfloat16* __restrict__ A0, const __nv_bfloat16* __restrict__ B0,
    int ld, int K, int nchunks, unsigned sm, float (*acc)[8][4])
{
    const int t = threadIdx.x;
    const int lane = t & 31, wid = t >> 5;
    const int wm = wid >> 1, wn = wid & 1;
    const unsigned bufA[2] = {sm, sm + 32768};
    const unsigned bufB[2] = {sm + 16384, sm + 49152};

    load_chunk(A0, B0, ld, acol_of(0, K), bcol_of(0, K), bufA[0], bufB[0], t);
    CP_COMMIT();

    for (int c = 0; c < nchunks; ++c) {
        if (c + 1 < nchunks) {
            load_chunk(A0, B0, ld, acol_of(c + 1, K), bcol_of(c + 1, K),
                       bufA[(c + 1) & 1], bufB[(c + 1) & 1], t);
            CP_COMMIT();
            CP_WAIT1();
        } else {
            CP_WAIT0();
        }
        __syncthreads();
        compute_stage(bufA[c & 1], bufB[c & 1], lane, wm, wn, acc);
        __syncthreads();
    }
}

// ---------------------------------------------------------------------------
// GEMM 1: h = relu(hs @ W^T + b), epilogue re-splits h -> g_h2 [8192, 512]
// M=8192, N=256, K=1024 (K_eff=3072, 48 chunks)
// ---------------------------------------------------------------------------
__global__ __launch_bounds__(256, 1) void gemm1_kernel(const float* __restrict__ bias)
{
    extern __shared__ char smem[];
    const unsigned sm = smem_u32(smem);
    const int t = threadIdx.x, lane = t & 31, wid = t >> 5;
    const int wm = wid >> 1, wn = wid & 1;
    const int row0 = blockIdx.y * 128;
    const int col0 = blockIdx.x * 128;

    float acc[2][8][4];
#pragma unroll
    for (int i = 0; i < 2; ++i)
#pragma unroll
        for (int j = 0; j < 8; ++j)
#pragma unroll
            for (int k = 0; k < 4; ++k) acc[i][j][k] = 0.f;

    gemm_main(g_hs2 + (size_t)row0 * 2048, g_w2 + (size_t)col0 * 2048,
              2048, 1024, 48, sm, acc);

    const int rb0 = row0 + wm * 32 + (lane >> 2);
    const int cb0 = col0 + wn * 64 + (lane & 3) * 2;
#pragma unroll
    for (int mi = 0; mi < 2; ++mi) {
#pragma unroll
        for (int ni = 0; ni < 8; ++ni) {
            const int c = cb0 + ni * 8;
            const float b0 = bias[c], b1 = bias[c + 1];
#pragma unroll
            for (int half = 0; half < 2; ++half) {      // half=0: row r, 1: r+8
                const int r = rb0 + mi * 16 + half * 8;
                float v0 = fmaxf(acc[mi][ni][2 * half]     + b0, 0.f);
                float v1 = fmaxf(acc[mi][ni][2 * half + 1] + b1, 0.f);
                __nv_bfloat16 h0 = __float2bfloat16(v0);
                __nv_bfloat16 h1 = __float2bfloat16(v1);
                __nv_bfloat16 l0 = __float2bfloat16(v0 - __bfloat162float(h0));
                __nv_bfloat16 l1 = __float2bfloat16(v1 - __bfloat162float(h1));
                __nv_bfloat16* rowp = g_h2 + (size_t)r * 512 + c;
                *reinterpret_cast<__nv_bfloat162*>(rowp)       = __halves2bfloat162(h0, h1);
                *reinterpret_cast<__nv_bfloat162*>(rowp + 256) = __halves2bfloat162(l0, l1);
            }
        }
    }
}

// ---------------------------------------------------------------------------
// GEMM 2: out[b,i,j] = (h_i . h_j) * cw + cb
// Per batch M=N=2048, K=256 (K_eff=768, 12 chunks)
// ---------------------------------------------------------------------------
__global__ __launch_bounds__(256, 1) void gemm2_kernel(
    const float* __restrict__ clf_w, const float* __restrict__ clf_b,
    float* __restrict__ out)
{
    extern __shared__ char smem[];
    const unsigned sm = smem_u32(smem);
    const int t = threadIdx.x, lane = t & 31, wid = t >> 5;
    const int wm = wid >> 1, wn = wid & 1;
    const int b    = blockIdx.z;
    const int row0 = blockIdx.y * 128;
    const int col0 = blockIdx.x * 128;

    float acc[2][8][4];
#pragma unroll
    for (int i = 0; i < 2; ++i)
#pragma unroll
        for (int j = 0; j < 8; ++j)
#pragma unroll
            for (int k = 0; k < 4; ++k) acc[i][j][k] = 0.f;

    const __nv_bfloat16* hb = g_h2 + (size_t)b * SEQ * 512;
    gemm_main(hb + (size_t)row0 * 512, hb + (size_t)col0 * 512,
              512, 256, 12, sm, acc);

    const float cw = __ldg(clf_w);
    const float cb = __ldg(clf_b);
    float* __restrict__ ob = out + (size_t)b * SEQ * SEQ;

    const int rb0 = row0 + wm * 32 + (lane >> 2);
    const int cb0 = col0 + wn * 64 + (lane & 3) * 2;
#pragma unroll
    for (int mi = 0; mi < 2; ++mi) {
#pragma unroll
        for (int ni = 0; ni < 8; ++ni) {
            const int c = cb0 + ni * 8;
#pragma unroll
            for (int half = 0; half < 2; ++half) {
                const int r = rb0 + mi * 16 + half * 8;
                float2 v;
                v.x = acc[mi][ni][2 * half]     * cw + cb;
                v.y = acc[mi][ni][2 * half + 1] * cw + cb;
                *reinterpret_cast<float2*>(ob + (size_t)r * SEQ + c) = v;
            }
        }
    }
}

// ---------------------------------------------------------------------------
extern "C" void kernel_launch(void* const* d_in, const int* in_sizes, int n_in,
                              void* d_out, int out_size)
{
    const float* hs     = (const float*)d_in[0];  // [4, 2048, 1024]
    const float* proj_w = (const float*)d_in[1];  // [256, 1024]
    const float* proj_b = (const float*)d_in[2];  // [256]
    const float* clf_w  = (const float*)d_in[3];  // [1, 1]
    const float* clf_b  = (const float*)d_in[4];  // [1]
    float* out = (float*)d_out;                   // [4, 2048, 2048]

    cudaFuncSetAttribute(gemm1_kernel,
                         cudaFuncAttributeMaxDynamicSharedMemorySize, SMEM_BYTES);
    cudaFuncSetAttribute(gemm2_kernel,
                         cudaFuncAttributeMaxDynamicSharedMemorySize, SMEM_BYTES);

    {   // split hs: 8192x1024 -> g_hs2 [8192, 2048]
        int n4 = 8192 * 1024 / 4;
        split_kernel<<<(n4 + 255) / 256, 256>>>(hs, 0, 1024, n4);
    }
    {   // split W: 256x1024 -> g_w2 [256, 2048]
        int n4 = 256 * 1024 / 4;
        split_kernel<<<(n4 + 255) / 256, 256>>>(proj_w, 1, 1024, n4);
    }
    {   // GEMM1: 64 x 2 tiles of 128x128
        dim3 grid(2, 64);
        gemm1_kernel<<<grid, 256, SMEM_BYTES>>>(proj_b);
    }
    {   // GEMM2: 16 x 16 x 4 tiles of 128x128
        dim3 grid(16, 16, BATCH);
        gemm2_kernel<<<grid, 256, SMEM_BYTES>>>(clf_w, clf_b, out);
    }
}

// round 7
// speedup vs baseline: 3.9114x; 1.8260x over previous
#include <cuda_runtime.h>
#include <cuda_bf16.h>
#include <cstdint>

#define BATCH 4
#define SEQ   2048

// Split operand storage: [rows, 2K] bf16, cols [0,K) = hi, [K,2K) = lo
__device__ __nv_bfloat16 g_hs2[(size_t)8192 * 2048];  // 32 MiB
__device__ __nv_bfloat16 g_w2 [(size_t)256  * 2048];  // 1 MiB
__device__ __nv_bfloat16 g_h2 [(size_t)8192 * 512];   // 8 MiB (h split, K=256)

// ---------------------------------------------------------------------------
// PTX helpers (sm_80-era instructions — valid at compute_103)
// ---------------------------------------------------------------------------
__device__ __forceinline__ unsigned smem_u32(const void* p) {
    unsigned a;
    asm("{ .reg .u64 t; cvta.to.shared.u64 t, %1; cvt.u32.u64 %0, t; }"
        : "=r"(a) : "l"(p));
    return a;
}

#define CP_ASYNC16(dst, src) \
    asm volatile("cp.async.cg.shared.global [%0], [%1], 16;" :: "r"(dst), "l"(src))
#define CP_COMMIT() asm volatile("cp.async.commit_group;" ::: "memory")
#define CP_WAIT1()  asm volatile("cp.async.wait_group 1;" ::: "memory")
#define CP_WAIT0()  asm volatile("cp.async.wait_group 0;" ::: "memory")

#define LDSM_X4(r0, r1, r2, r3, a) \
    asm volatile("ldmatrix.sync.aligned.m8n8.x4.shared.b16 {%0,%1,%2,%3}, [%4];" \
                 : "=r"(r0), "=r"(r1), "=r"(r2), "=r"(r3) : "r"(a))

#define MMA16816(d, a, b0, b1) \
    asm volatile( \
        "mma.sync.aligned.m16n8k16.row.col.f32.bf16.bf16.f32 " \
        "{%0,%1,%2,%3},{%4,%5,%6,%7},{%8,%9},{%0,%1,%2,%3};" \
        : "+f"((d)[0]), "+f"((d)[1]), "+f"((d)[2]), "+f"((d)[3]) \
        : "r"((a)[0]), "r"((a)[1]), "r"((a)[2]), "r"((a)[3]), "r"(b0), "r"(b1))

// 3-stage ring: each stage = A(16KB) + B(16KB) = 32KB; 3 stages = 96KB
#define STAGE_BYTES 32768
#define SMEM_BYTES  98304

// ---------------------------------------------------------------------------
// Split fp32 -> (hi, lo) bf16, layout [R, 2C]: hi cols [0,C), lo cols [C,2C)
// ---------------------------------------------------------------------------
__global__ __launch_bounds__(256) void split_kernel(const float* __restrict__ src,
                                                    int which, int C, int n4) {
    int i = blockIdx.x * blockDim.x + threadIdx.x;
    if (i >= n4) return;
    __nv_bfloat16* __restrict__ dst = which ? g_w2 : g_hs2;
    int e0 = i * 4;
    int r = e0 / C, c = e0 - r * C;
    float4 v = *reinterpret_cast<const float4*>(src + e0);

    __nv_bfloat16 h0 = __float2bfloat16(v.x), h1 = __float2bfloat16(v.y);
    __nv_bfloat16 h2 = __float2bfloat16(v.z), h3 = __float2bfloat16(v.w);
    __nv_bfloat16 l0 = __float2bfloat16(v.x - __bfloat162float(h0));
    __nv_bfloat16 l1 = __float2bfloat16(v.y - __bfloat162float(h1));
    __nv_bfloat16 l2 = __float2bfloat16(v.z - __bfloat162float(h2));
    __nv_bfloat16 l3 = __float2bfloat16(v.w - __bfloat162float(h3));

    __nv_bfloat16* rowp = dst + (size_t)r * (2 * C);
    *reinterpret_cast<__nv_bfloat162*>(rowp + c)         = __halves2bfloat162(h0, h1);
    *reinterpret_cast<__nv_bfloat162*>(rowp + c + 2)     = __halves2bfloat162(h2, h3);
    *reinterpret_cast<__nv_bfloat162*>(rowp + C + c)     = __halves2bfloat162(l0, l1);
    *reinterpret_cast<__nv_bfloat162*>(rowp + C + c + 2) = __halves2bfloat162(l2, l3);
}

// ---------------------------------------------------------------------------
// 3-term split K-chunk column mapping over [R, 2K] storage.
//   term0: ahi*bhi   term1: alo*bhi   term2: ahi*blo   (alo*blo dropped, ~4e-6)
// ---------------------------------------------------------------------------
__device__ __forceinline__ int acol_of(int c, int K) {
    int kk = c * 64; return kk < 2 * K ? kk : kk - 2 * K;
}
__device__ __forceinline__ int bcol_of(int c, int K) {
    int kk = c * 64; return kk < K ? kk : kk - K;
}

// Load one 128x64-bf16 chunk per operand into a smem stage (xor-swizzled)
__device__ __forceinline__ void load_chunk(
    const __nv_bfloat16* __restrict__ Abase, const __nv_bfloat16* __restrict__ Bbase,
    int ld, int ac, int bc, unsigned sA, unsigned sB, int t)
{
#pragma unroll
    for (int i = 0; i < 4; ++i) {
        int idx = t + i * 256;          // 0..1023: 128 rows x 8 16B-chunks
        int row = idx >> 3, ch = idx & 7;
        unsigned dst = (unsigned)(row * 128 + ((ch ^ (row & 7)) << 4));
        const void* srcA = Abase + (size_t)row * ld + ac + ch * 8;
        const void* srcB = Bbase + (size_t)row * ld + bc + ch * 8;
        CP_ASYNC16(sA + dst, srcA);
        CP_ASYNC16(sB + dst, srcB);
    }
}

// Compute 4 k16-steps from one smem stage. Warp tile 32(M) x 64(N).
__device__ __forceinline__ void compute_stage(
    unsigned sA, unsigned sB, int lane, int wm, int wn, float (*acc)[8][4])
{
#pragma unroll
    for (int s = 0; s < 4; ++s) {
        const int ch = s * 2 + (lane >> 4);
        unsigned a[2][4], rb[4][4];
#pragma unroll
        for (int mi = 0; mi < 2; ++mi) {
            int row = wm * 32 + mi * 16 + (lane & 15);
            unsigned addr = sA + row * 128 + ((ch ^ (row & 7)) << 4);
            LDSM_X4(a[mi][0], a[mi][1], a[mi][2], a[mi][3], addr);
        }
#pragma unroll
        for (int p = 0; p < 4; ++p) {
            int row = wn * 64 + p * 16 + (lane & 15);
            unsigned addr = sB + row * 128 + ((ch ^ (row & 7)) << 4);
            LDSM_X4(rb[p][0], rb[p][1], rb[p][2], rb[p][3], addr);
        }
#pragma unroll
        for (int mi = 0; mi < 2; ++mi)
#pragma unroll
            for (int p = 0; p < 4; ++p) {
                MMA16816(acc[mi][2 * p],     a[mi], rb[p][0], rb[p][2]);
                MMA16816(acc[mi][2 * p + 1], a[mi], rb[p][1], rb[p][3]);
            }
    }
}

// Mainloop: 3-stage cp.async ring, ONE __syncthreads per chunk.
__device__ __forceinline__ void gemm_main(
    const __nv_bfloat16* __restrict__ A0, const __nv_bfloat16* __restrict__ B0,
    int ld, int K, int nchunks, unsigned sm, float (*acc)[8][4])
{
    const int t = threadIdx.x;
    const int lane = t & 31, wid = t >> 5;
    const int wm = wid >> 1, wn = wid & 1;
    const unsigned bufA[3] = {sm, sm + STAGE_BYTES, sm + 2 * STAGE_BYTES};
    const unsigned bufB[3] = {sm + 16384, sm + STAGE_BYTES + 16384,
                              sm + 2 * STAGE_BYTES + 16384};

    load_chunk(A0, B0, ld, acol_of(0, K), bcol_of(0, K), bufA[0], bufB[0], t);
    CP_COMMIT();
    load_chunk(A0, B0, ld, acol_of(1, K), bcol_of(1, K), bufA[1], bufB[1], t);
    CP_COMMIT();

    for (int c = 0; c < nchunks; ++c) {
        if (c + 1 < nchunks) CP_WAIT1(); else CP_WAIT0();
        __syncthreads();
        const int p = c + 2;
        if (p < nchunks) {
            load_chunk(A0, B0, ld, acol_of(p, K), bcol_of(p, K),
                       bufA[p % 3], bufB[p % 3], t);
            CP_COMMIT();
        }
        compute_stage(bufA[c % 3], bufB[c % 3], lane, wm, wn, acc);
    }
    __syncthreads();   // smem safe to reuse by epilogue
}

// ---------------------------------------------------------------------------
// GEMM 1: h = relu(hs @ W^T + b), epilogue re-splits h -> g_h2 [8192, 512]
// M=8192, N=256, K=1024 (K_eff=3072, 48 chunks)
// ---------------------------------------------------------------------------
__global__ __launch_bounds__(256, 1) void gemm1_kernel(const float* __restrict__ bias)
{
    extern __shared__ char smem[];
    const unsigned sm = smem_u32(smem);
    const int t = threadIdx.x, lane = t & 31, wid = t >> 5;
    const int wm = wid >> 1, wn = wid & 1;
    const int row0 = blockIdx.y * 128;
    const int col0 = blockIdx.x * 128;

    float acc[2][8][4];
#pragma unroll
    for (int i = 0; i < 2; ++i)
#pragma unroll
        for (int j = 0; j < 8; ++j)
#pragma unroll
            for (int k = 0; k < 4; ++k) acc[i][j][k] = 0.f;

    gemm_main(g_hs2 + (size_t)row0 * 2048, g_w2 + (size_t)col0 * 2048,
              2048, 1024, 48, sm, acc);

    const int rb0 = row0 + wm * 32 + (lane >> 2);
    const int cb0 = col0 + wn * 64 + (lane & 3) * 2;
#pragma unroll
    for (int mi = 0; mi < 2; ++mi) {
#pragma unroll
        for (int ni = 0; ni < 8; ++ni) {
            const int c = cb0 + ni * 8;
            const float b0 = bias[c], b1 = bias[c + 1];
#pragma unroll
            for (int half = 0; half < 2; ++half) {      // half=0: row r, 1: r+8
                const int r = rb0 + mi * 16 + half * 8;
                float v0 = fmaxf(acc[mi][ni][2 * half]     + b0, 0.f);
                float v1 = fmaxf(acc[mi][ni][2 * half + 1] + b1, 0.f);
                __nv_bfloat16 h0 = __float2bfloat16(v0);
                __nv_bfloat16 h1 = __float2bfloat16(v1);
                __nv_bfloat16 l0 = __float2bfloat16(v0 - __bfloat162float(h0));
                __nv_bfloat16 l1 = __float2bfloat16(v1 - __bfloat162float(h1));
                __nv_bfloat16* rowp = g_h2 + (size_t)r * 512 + c;
                *reinterpret_cast<__nv_bfloat162*>(rowp)       = __halves2bfloat162(h0, h1);
                *reinterpret_cast<__nv_bfloat162*>(rowp + 256) = __halves2bfloat162(l0, l1);
            }
        }
    }
}

// ---------------------------------------------------------------------------
// GEMM 2: out[b,i,j] = (h_i . h_j) * cw + cb, exploiting symmetry.
// Only upper-triangular tiles (ti <= tj) computed: 136 of 256 per batch.
// Off-diagonal tiles also write their transpose via smem staging.
// ---------------------------------------------------------------------------
__global__ __launch_bounds__(256, 1) void gemm2_kernel(
    const float* __restrict__ clf_w, const float* __restrict__ clf_b,
    float* __restrict__ out)
{
    extern __shared__ char smem[];
    const unsigned sm = smem_u32(smem);
    const int t = threadIdx.x, lane = t & 31, wid = t >> 5;
    const int wm = wid >> 1, wn = wid & 1;
    const int b = blockIdx.z;

    // Map linear tile index -> (ti, tj) with ti <= tj over a 16x16 tile grid
    int ti = 0, rem = blockIdx.x;
    while (rem >= 16 - ti) { rem -= 16 - ti; ++ti; }
    const int tj = ti + rem;
    const int row0 = ti * 128;
    const int col0 = tj * 128;

    float acc[2][8][4];
#pragma unroll
    for (int i = 0; i < 2; ++i)
#pragma unroll
        for (int j = 0; j < 8; ++j)
#pragma unroll
            for (int k = 0; k < 4; ++k) acc[i][j][k] = 0.f;

    const __nv_bfloat16* hb = g_h2 + (size_t)b * SEQ * 512;
    gemm_main(hb + (size_t)row0 * 512, hb + (size_t)col0 * 512,
              512, 256, 12, sm, acc);

    const float cw = __ldg(clf_w);
    const float cb = __ldg(clf_b);
    float* __restrict__ ob = out + (size_t)b * SEQ * SEQ;

    float* tileT = reinterpret_cast<float*>(smem);   // [128][132] transposed stage
    const bool diag = (ti == tj);

    const int rloc = wm * 32 + (lane >> 2);
    const int cloc = wn * 64 + (lane & 3) * 2;
#pragma unroll
    for (int mi = 0; mi < 2; ++mi) {
#pragma unroll
        for (int ni = 0; ni < 8; ++ni) {
            const int c = cloc + ni * 8;
#pragma unroll
            for (int half = 0; half < 2; ++half) {
                const int r = rloc + mi * 16 + half * 8;
                float2 v;
                v.x = acc[mi][ni][2 * half]     * cw + cb;
                v.y = acc[mi][ni][2 * half + 1] * cw + cb;
                *reinterpret_cast<float2*>(
                    ob + (size_t)(row0 + r) * SEQ + col0 + c) = v;
                if (!diag) {
                    tileT[(c)     * 132 + r] = v.x;
                    tileT[(c + 1) * 132 + r] = v.y;
                }
            }
        }
    }

    if (!diag) {
        __syncthreads();
        // Coalesced mirror write: out[col0+row, row0..row0+127]
        for (int i = t; i < 128 * 32; i += 256) {
            const int row = i >> 5, q = (i & 31) * 4;
            float4 v = *reinterpret_cast<const float4*>(&tileT[row * 132 + q]);
            *reinterpret_cast<float4*>(
                ob + (size_t)(col0 + row) * SEQ + row0 + q) = v;
        }
    }
}

// ---------------------------------------------------------------------------
extern "C" void kernel_launch(void* const* d_in, const int* in_sizes, int n_in,
                              void* d_out, int out_size)
{
    const float* hs     = (const float*)d_in[0];  // [4, 2048, 1024]
    const float* proj_w = (const float*)d_in[1];  // [256, 1024]
    const float* proj_b = (const float*)d_in[2];  // [256]
    const float* clf_w  = (const float*)d_in[3];  // [1, 1]
    const float* clf_b  = (const float*)d_in[4];  // [1]
    float* out = (float*)d_out;                   // [4, 2048, 2048]

    cudaFuncSetAttribute(gemm1_kernel,
                         cudaFuncAttributeMaxDynamicSharedMemorySize, SMEM_BYTES);
    cudaFuncSetAttribute(gemm2_kernel,
                         cudaFuncAttributeMaxDynamicSharedMemorySize, SMEM_BYTES);

    {   // split hs: 8192x1024 -> g_hs2 [8192, 2048]
        int n4 = 8192 * 1024 / 4;
        split_kernel<<<(n4 + 255) / 256, 256>>>(hs, 0, 1024, n4);
    }
    {   // split W: 256x1024 -> g_w2 [256, 2048]
        int n4 = 256 * 1024 / 4;
        split_kernel<<<(n4 + 255) / 256, 256>>>(proj_w, 1, 1024, n4);
    }
    {   // GEMM1: 2 x 64 tiles of 128x128
        dim3 grid(2, 64);
        gemm1_kernel<<<grid, 256, SMEM_BYTES>>>(proj_b);
    }
    {   // GEMM2: 136 upper-tri tiles x 4 batches
        dim3 grid(136, 1, BATCH);
        gemm2_kernel<<<grid, 256, SMEM_BYTES>>>(clf_w, clf_b, out);
    }
}

// round 8
// speedup vs baseline: 4.2508x; 1.0868x over previous
#include <cuda_runtime.h>
#include <cuda_bf16.h>
#include <cstdint>

#define BATCH 4
#define SEQ   2048

// Split operand storage: [rows, 2K] bf16, cols [0,K) = hi, [K,2K) = lo
__device__ __nv_bfloat16 g_hs2[(size_t)8192 * 2048];  // 32 MiB
__device__ __nv_bfloat16 g_w2 [(size_t)256  * 2048];  // 1 MiB
__device__ __nv_bfloat16 g_h2 [(size_t)8192 * 512];   // 8 MiB (h split, K=256)

// ---------------------------------------------------------------------------
// PTX helpers
// ---------------------------------------------------------------------------
__device__ __forceinline__ unsigned smem_u32(const void* p) {
    unsigned a;
    asm("{ .reg .u64 t; cvta.to.shared.u64 t, %1; cvt.u32.u64 %0, t; }"
        : "=r"(a) : "l"(p));
    return a;
}

#define CP_ASYNC16(dst, src) \
    asm volatile("cp.async.cg.shared.global [%0], [%1], 16;" :: "r"(dst), "l"(src))
#define CP_COMMIT() asm volatile("cp.async.commit_group;" ::: "memory")
#define CP_WAIT1()  asm volatile("cp.async.wait_group 1;" ::: "memory")
#define CP_WAIT0()  asm volatile("cp.async.wait_group 0;" ::: "memory")

#define LDSM_X4(r0, r1, r2, r3, a) \
    asm volatile("ldmatrix.sync.aligned.m8n8.x4.shared.b16 {%0,%1,%2,%3}, [%4];" \
                 : "=r"(r0), "=r"(r1), "=r"(r2), "=r"(r3) : "r"(a))

#define MMA16816(d, a, b0, b1) \
    asm volatile( \
        "mma.sync.aligned.m16n8k16.row.col.f32.bf16.bf16.f32 " \
        "{%0,%1,%2,%3},{%4,%5,%6,%7},{%8,%9},{%0,%1,%2,%3};" \
        : "+f"((d)[0]), "+f"((d)[1]), "+f"((d)[2]), "+f"((d)[3]) \
        : "r"((a)[0]), "r"((a)[1]), "r"((a)[2]), "r"((a)[3]), "r"(b0), "r"(b1))

// gemm2: stage = A(16KB)+B(16KB) = 32KB, 3 stages = 96KB
#define G2_STAGE  32768
#define G2_SMEM   98304
// gemm1: stage = A(8KB)+B(16KB) = 24KB, 3 stages = 72KB
#define G1_STAGE  24576
#define G1_SMEM   73728

// ---------------------------------------------------------------------------
// Split fp32 -> (hi, lo) bf16, layout [R, 2C]: hi cols [0,C), lo cols [C,2C)
// ---------------------------------------------------------------------------
__global__ __launch_bounds__(256) void split_kernel(const float* __restrict__ src,
                                                    int which, int C, int n4) {
    int i = blockIdx.x * blockDim.x + threadIdx.x;
    if (i >= n4) return;
    __nv_bfloat16* __restrict__ dst = which ? g_w2 : g_hs2;
    int e0 = i * 4;
    int r = e0 / C, c = e0 - r * C;
    float4 v = *reinterpret_cast<const float4*>(src + e0);

    __nv_bfloat16 h0 = __float2bfloat16(v.x), h1 = __float2bfloat16(v.y);
    __nv_bfloat16 h2 = __float2bfloat16(v.z), h3 = __float2bfloat16(v.w);
    __nv_bfloat16 l0 = __float2bfloat16(v.x - __bfloat162float(h0));
    __nv_bfloat16 l1 = __float2bfloat16(v.y - __bfloat162float(h1));
    __nv_bfloat16 l2 = __float2bfloat16(v.z - __bfloat162float(h2));
    __nv_bfloat16 l3 = __float2bfloat16(v.w - __bfloat162float(h3));

    __nv_bfloat16* rowp = dst + (size_t)r * (2 * C);
    *reinterpret_cast<__nv_bfloat162*>(rowp + c)         = __halves2bfloat162(h0, h1);
    *reinterpret_cast<__nv_bfloat162*>(rowp + c + 2)     = __halves2bfloat162(h2, h3);
    *reinterpret_cast<__nv_bfloat162*>(rowp + C + c)     = __halves2bfloat162(l0, l1);
    *reinterpret_cast<__nv_bfloat162*>(rowp + C + c + 2) = __halves2bfloat162(l2, l3);
}

// ---------------------------------------------------------------------------
// 3-term split K-chunk mapping: term0 ahi*bhi, term1 alo*bhi, term2 ahi*blo
// ---------------------------------------------------------------------------
__device__ __forceinline__ int acol_of(int c, int K) {
    int kk = c * 64; return kk < 2 * K ? kk : kk - 2 * K;
}
__device__ __forceinline__ int bcol_of(int c, int K) {
    int kk = c * 64; return kk < K ? kk : kk - K;
}

// Load a ROWS x 64-bf16 chunk into smem (xor-swizzled). ROWS*8 transfers.
template<int ROWS>
__device__ __forceinline__ void load_op(
    const __nv_bfloat16* __restrict__ base, int ld, int col, unsigned s, int t)
{
#pragma unroll
    for (int i = 0; i < ROWS / 32; ++i) {
        int idx = t + i * 256;
        int row = idx >> 3, ch = idx & 7;
        unsigned dst = (unsigned)(row * 128 + ((ch ^ (row & 7)) << 4));
        CP_ASYNC16(s + dst, base + (size_t)row * ld + col + ch * 8);
    }
}

// Compute 4 k16-steps. Warp covers MI*16 (M) x NP*16 (N).
template<int MI, int NP>
__device__ __forceinline__ void compute_stage_t(
    unsigned sA, unsigned sB, int lane, int mrow0, int nrow0,
    float (&acc)[MI][2 * NP][4])
{
#pragma unroll
    for (int s = 0; s < 4; ++s) {
        const int ch = s * 2 + (lane >> 4);
        unsigned a[MI][4], rb[NP][4];
#pragma unroll
        for (int mi = 0; mi < MI; ++mi) {
            int row = mrow0 + mi * 16 + (lane & 15);
            unsigned addr = sA + row * 128 + ((ch ^ (row & 7)) << 4);
            LDSM_X4(a[mi][0], a[mi][1], a[mi][2], a[mi][3], addr);
        }
#pragma unroll
        for (int p = 0; p < NP; ++p) {
            int row = nrow0 + p * 16 + (lane & 15);
            unsigned addr = sB + row * 128 + ((ch ^ (row & 7)) << 4);
            LDSM_X4(rb[p][0], rb[p][1], rb[p][2], rb[p][3], addr);
        }
#pragma unroll
        for (int mi = 0; mi < MI; ++mi)
#pragma unroll
            for (int p = 0; p < NP; ++p) {
                MMA16816(acc[mi][2 * p],     a[mi], rb[p][0], rb[p][2]);
                MMA16816(acc[mi][2 * p + 1], a[mi], rb[p][1], rb[p][3]);
            }
    }
}

// ---------------------------------------------------------------------------
// GEMM 1: h = relu(hs @ W^T + b), re-split -> g_h2 [8192, 512]
// CTA tile 64(M) x 128(N); warp grid 2x4 (warp tile 32x32); 256 CTAs.
// K=1024 (K_eff=3072, 48 chunks)
// ---------------------------------------------------------------------------
__global__ __launch_bounds__(256, 2) void gemm1_kernel(const float* __restrict__ bias)
{
    extern __shared__ char smem[];
    const unsigned sm = smem_u32(smem);
    const int t = threadIdx.x, lane = t & 31, wid = t >> 5;
    const int wm = wid >> 2, wn = wid & 3;
    const int row0 = blockIdx.y * 64;
    const int col0 = blockIdx.x * 128;

    float acc[2][4][4];
#pragma unroll
    for (int i = 0; i < 2; ++i)
#pragma unroll
        for (int j = 0; j < 4; ++j)
#pragma unroll
            for (int k = 0; k < 4; ++k) acc[i][j][k] = 0.f;

    const __nv_bfloat16* A0 = g_hs2 + (size_t)row0 * 2048;
    const __nv_bfloat16* B0 = g_w2 + (size_t)col0 * 2048;
    const int K = 1024, nchunks = 48;

    unsigned bufA[3], bufB[3];
#pragma unroll
    for (int s = 0; s < 3; ++s) {
        bufA[s] = sm + s * G1_STAGE;
        bufB[s] = sm + s * G1_STAGE + 8192;
    }

    load_op<64>(A0, 2048, acol_of(0, K), bufA[0], t);
    load_op<128>(B0, 2048, bcol_of(0, K), bufB[0], t);
    CP_COMMIT();
    load_op<64>(A0, 2048, acol_of(1, K), bufA[1], t);
    load_op<128>(B0, 2048, bcol_of(1, K), bufB[1], t);
    CP_COMMIT();

    for (int c = 0; c < nchunks; ++c) {
        if (c + 1 < nchunks) CP_WAIT1(); else CP_WAIT0();
        __syncthreads();
        const int p = c + 2;
        if (p < nchunks) {
            load_op<64>(A0, 2048, acol_of(p, K), bufA[p % 3], t);
            load_op<128>(B0, 2048, bcol_of(p, K), bufB[p % 3], t);
            CP_COMMIT();
        }
        compute_stage_t<2, 2>(bufA[c % 3], bufB[c % 3], lane,
                              wm * 32, wn * 32, acc);
    }

    const int rb0 = row0 + wm * 32 + (lane >> 2);
    const int cb0 = col0 + wn * 32 + (lane & 3) * 2;
#pragma unroll
    for (int mi = 0; mi < 2; ++mi) {
#pragma unroll
        for (int ni = 0; ni < 4; ++ni) {
            const int c = cb0 + ni * 8;
            const float b0 = bias[c], b1 = bias[c + 1];
#pragma unroll
            for (int half = 0; half < 2; ++half) {
                const int r = rb0 + mi * 16 + half * 8;
                float v0 = fmaxf(acc[mi][ni][2 * half]     + b0, 0.f);
                float v1 = fmaxf(acc[mi][ni][2 * half + 1] + b1, 0.f);
                __nv_bfloat16 h0 = __float2bfloat16(v0);
                __nv_bfloat16 h1 = __float2bfloat16(v1);
                __nv_bfloat16 l0 = __float2bfloat16(v0 - __bfloat162float(h0));
                __nv_bfloat16 l1 = __float2bfloat16(v1 - __bfloat162float(h1));
                __nv_bfloat16* rowp = g_h2 + (size_t)r * 512 + c;
                *reinterpret_cast<__nv_bfloat162*>(rowp)       = __halves2bfloat162(h0, h1);
                *reinterpret_cast<__nv_bfloat162*>(rowp + 256) = __halves2bfloat162(l0, l1);
            }
        }
    }
}

// ---------------------------------------------------------------------------
// GEMM 2: out[b,i,j] = (h_i . h_j) * cw + cb, symmetric — upper-tri tiles only.
// CTA tile 128x128; warp grid 4x2 (warp tile 32x64). 2 CTAs/SM.
// ---------------------------------------------------------------------------
__global__ __launch_bounds__(256, 2) void gemm2_kernel(
    const float* __restrict__ clf_w, const float* __restrict__ clf_b,
    float* __restrict__ out)
{
    extern __shared__ char smem[];
    const unsigned sm = smem_u32(smem);
    const int t = threadIdx.x, lane = t & 31, wid = t >> 5;
    const int wm = wid >> 1, wn = wid & 1;
    const int b = blockIdx.z;

    // Map linear tile index -> (ti, tj) with ti <= tj over a 16x16 tile grid
    int ti = 0, rem = blockIdx.x;
    while (rem >= 16 - ti) { rem -= 16 - ti; ++ti; }
    const int tj = ti + rem;
    const int row0 = ti * 128;
    const int col0 = tj * 128;

    float acc[2][8][4];
#pragma unroll
    for (int i = 0; i < 2; ++i)
#pragma unroll
        for (int j = 0; j < 8; ++j)
#pragma unroll
            for (int k = 0; k < 4; ++k) acc[i][j][k] = 0.f;

    const __nv_bfloat16* hb = g_h2 + (size_t)b * SEQ * 512;
    const __nv_bfloat16* A0 = hb + (size_t)row0 * 512;
    const __nv_bfloat16* B0 = hb + (size_t)col0 * 512;
    const int K = 256, nchunks = 12;

    unsigned bufA[3], bufB[3];
#pragma unroll
    for (int s = 0; s < 3; ++s) {
        bufA[s] = sm + s * G2_STAGE;
        bufB[s] = sm + s * G2_STAGE + 16384;
    }

    load_op<128>(A0, 512, acol_of(0, K), bufA[0], t);
    load_op<128>(B0, 512, bcol_of(0, K), bufB[0], t);
    CP_COMMIT();
    load_op<128>(A0, 512, acol_of(1, K), bufA[1], t);
    load_op<128>(B0, 512, bcol_of(1, K), bufB[1], t);
    CP_COMMIT();

    for (int c = 0; c < nchunks; ++c) {
        if (c + 1 < nchunks) CP_WAIT1(); else CP_WAIT0();
        __syncthreads();
        const int p = c + 2;
        if (p < nchunks) {
            load_op<128>(A0, 512, acol_of(p, K), bufA[p % 3], t);
            load_op<128>(B0, 512, bcol_of(p, K), bufB[p % 3], t);
            CP_COMMIT();
        }
        compute_stage_t<2, 4>(bufA[c % 3], bufB[c % 3], lane,
                              wm * 32, wn * 64, acc);
    }
    __syncthreads();   // smem safe for epilogue reuse

    const float cw = __ldg(clf_w);
    const float cb = __ldg(clf_b);
    float* __restrict__ ob = out + (size_t)b * SEQ * SEQ;

    float* tileT = reinterpret_cast<float*>(smem);   // [128][132] transposed stage
    const bool diag = (ti == tj);

    const int rloc = wm * 32 + (lane >> 2);
    const int cloc = wn * 64 + (lane & 3) * 2;
#pragma unroll
    for (int mi = 0; mi < 2; ++mi) {
#pragma unroll
        for (int ni = 0; ni < 8; ++ni) {
            const int c = cloc + ni * 8;
#pragma unroll
            for (int half = 0; half < 2; ++half) {
                const int r = rloc + mi * 16 + half * 8;
                float2 v;
                v.x = acc[mi][ni][2 * half]     * cw + cb;
                v.y = acc[mi][ni][2 * half + 1] * cw + cb;
                *reinterpret_cast<float2*>(
                    ob + (size_t)(row0 + r) * SEQ + col0 + c) = v;
                if (!diag) {
                    tileT[(c)     * 132 + r] = v.x;
                    tileT[(c + 1) * 132 + r] = v.y;
                }
            }
        }
    }

    if (!diag) {
        __syncthreads();
        for (int i = t; i < 128 * 32; i += 256) {
            const int row = i >> 5, q = (i & 31) * 4;
            float4 v = *reinterpret_cast<const float4*>(&tileT[row * 132 + q]);
            *reinterpret_cast<float4*>(
                ob + (size_t)(col0 + row) * SEQ + row0 + q) = v;
        }
    }
}

// ---------------------------------------------------------------------------
extern "C" void kernel_launch(void* const* d_in, const int* in_sizes, int n_in,
                              void* d_out, int out_size)
{
    const float* hs     = (const float*)d_in[0];  // [4, 2048, 1024]
    const float* proj_w = (const float*)d_in[1];  // [256, 1024]
    const float* proj_b = (const float*)d_in[2];  // [256]
    const float* clf_w  = (const float*)d_in[3];  // [1, 1]
    const float* clf_b  = (const float*)d_in[4];  // [1]
    float* out = (float*)d_out;                   // [4, 2048, 2048]

    cudaFuncSetAttribute(gemm1_kernel,
                         cudaFuncAttributeMaxDynamicSharedMemorySize, G1_SMEM);
    cudaFuncSetAttribute(gemm2_kernel,
                         cudaFuncAttributeMaxDynamicSharedMemorySize, G2_SMEM);

    {   // split hs: 8192x1024 -> g_hs2 [8192, 2048]
        int n4 = 8192 * 1024 / 4;
        split_kernel<<<(n4 + 255) / 256, 256>>>(hs, 0, 1024, n4);
    }
    {   // split W: 256x1024 -> g_w2 [256, 2048]
        int n4 = 256 * 1024 / 4;
        split_kernel<<<(n4 + 255) / 256, 256>>>(proj_w, 1, 1024, n4);
    }
    {   // GEMM1: 2 x 128 tiles of 64x128
        dim3 grid(2, 128);
        gemm1_kernel<<<grid, 256, G1_SMEM>>>(proj_b);
    }
    {   // GEMM2: 136 upper-tri tiles x 4 batches
        dim3 grid(136, 1, BATCH);
        gemm2_kernel<<<grid, 256, G2_SMEM>>>(clf_w, clf_b, out);
    }
}

// round 10
// speedup vs baseline: 6.0314x; 1.4189x over previous
#include <cuda_runtime.h>
#include <cuda_fp16.h>
#include <cstdint>

#define BATCH 4
#define SEQ   2048

// fp16 2-term split storage.
// A-role operands store [R, 2K] = [hi | lo]; B-role operands store hi only.
__device__ __half g_hs2[(size_t)8192 * 2048];  // hs: A of gemm1 (hi|lo), 32 MiB
__device__ __half g_w2 [(size_t)256  * 1024];  // W: B of gemm1 (hi only), 0.5 MiB
__device__ __half g_h2 [(size_t)8192 * 512];   // h: A(hi|lo) + B(hi half) of gemm2

// ---------------------------------------------------------------------------
// PTX helpers
// ---------------------------------------------------------------------------
__device__ __forceinline__ unsigned smem_u32(const void* p) {
    unsigned a;
    asm("{ .reg .u64 t; cvta.to.shared.u64 t, %1; cvt.u32.u64 %0, t; }"
        : "=r"(a) : "l"(p));
    return a;
}

#define CP_ASYNC16(dst, src) \
    asm volatile("cp.async.cg.shared.global [%0], [%1], 16;" :: "r"(dst), "l"(src))
#define CP_COMMIT() asm volatile("cp.async.commit_group;" ::: "memory")
#define CP_WAIT1()  asm volatile("cp.async.wait_group 1;" ::: "memory")
#define CP_WAIT0()  asm volatile("cp.async.wait_group 0;" ::: "memory")

#define LDSM_X4(r0, r1, r2, r3, a) \
    asm volatile("ldmatrix.sync.aligned.m8n8.x4.shared.b16 {%0,%1,%2,%3}, [%4];" \
                 : "=r"(r0), "=r"(r1), "=r"(r2), "=r"(r3) : "r"(a))

#define MMA16816(d, a, b0, b1) \
    asm volatile( \
        "mma.sync.aligned.m16n8k16.row.col.f32.f16.f16.f32 " \
        "{%0,%1,%2,%3},{%4,%5,%6,%7},{%8,%9},{%0,%1,%2,%3};" \
        : "+f"((d)[0]), "+f"((d)[1]), "+f"((d)[2]), "+f"((d)[3]) \
        : "r"((a)[0]), "r"((a)[1]), "r"((a)[2]), "r"((a)[3]), "r"(b0), "r"(b1))

// gemm2: stage = A(16KB)+B(16KB) = 32KB, 3 stages = 96KB
#define G2_STAGE  32768
#define G2_SMEM   98304
// gemm1: stage = A(8KB)+B(16KB) = 24KB, 3 stages = 72KB
#define G1_STAGE  24576
#define G1_SMEM   73728

// ---------------------------------------------------------------------------
// Combined split kernel.
//   part 0 (i < n4_hs): hs fp32 [8192,1024] -> g_hs2 [8192, 2048] (hi|lo)
//   part 1 (rest):      W  fp32 [256,1024]  -> g_w2  [256, 1024]  (hi only)
// ---------------------------------------------------------------------------
__global__ __launch_bounds__(256) void split_kernel(
    const float* __restrict__ hs, const float* __restrict__ W,
    int n4_hs, int n4_w)
{
    int i = blockIdx.x * blockDim.x + threadIdx.x;
    if (i < n4_hs) {
        int e0 = i * 4;
        int r = e0 >> 10, c = e0 & 1023;             // C = 1024
        float4 v = *reinterpret_cast<const float4*>(hs + e0);
        __half h0 = __float2half_rn(v.x), h1 = __float2half_rn(v.y);
        __half h2 = __float2half_rn(v.z), h3 = __float2half_rn(v.w);
        __half l0 = __float2half_rn(v.x - __half2float(h0));
        __half l1 = __float2half_rn(v.y - __half2float(h1));
        __half l2 = __float2half_rn(v.z - __half2float(h2));
        __half l3 = __float2half_rn(v.w - __half2float(h3));
        __half* rowp = g_hs2 + (size_t)r * 2048;
        *reinterpret_cast<__half2*>(rowp + c)           = __halves2half2(h0, h1);
        *reinterpret_cast<__half2*>(rowp + c + 2)       = __halves2half2(h2, h3);
        *reinterpret_cast<__half2*>(rowp + 1024 + c)     = __halves2half2(l0, l1);
        *reinterpret_cast<__half2*>(rowp + 1024 + c + 2) = __halves2half2(l2, l3);
    } else {
        int j = i - n4_hs;
        if (j >= n4_w) return;
        int e0 = j * 4;
        float4 v = *reinterpret_cast<const float4*>(W + e0);
        __half2 p0 = __halves2half2(__float2half_rn(v.x), __float2half_rn(v.y));
        __half2 p1 = __halves2half2(__float2half_rn(v.z), __float2half_rn(v.w));
        *reinterpret_cast<__half2*>(g_w2 + e0)     = p0;
        *reinterpret_cast<__half2*>(g_w2 + e0 + 2) = p1;
    }
}

// ---------------------------------------------------------------------------
// 2-term mapping: chunk c covers kk = c*64 of K_eff = 2K.
//   term0 (kk <  K): ahi * bhi  -> a col kk (hi region),  b col kk
//   term1 (kk >= K): alo * bhi  -> a col kk (lo region),  b col kk-K
// A layout is [R, 2K] so a col == kk directly.
// ---------------------------------------------------------------------------
__device__ __forceinline__ int bcol_of(int c, int K) {
    int kk = c * 64; return kk < K ? kk : kk - K;
}

// Load a ROWS x 64-fp16 chunk into smem (xor-swizzled, 128B rows).
template<int ROWS>
__device__ __forceinline__ void load_op(
    const __half* __restrict__ base, int ld, int col, unsigned s, int t)
{
#pragma unroll
    for (int i = 0; i < ROWS / 32; ++i) {
        int idx = t + i * 256;
        int row = idx >> 3, ch = idx & 7;
        unsigned dst = (unsigned)(row * 128 + ((ch ^ (row & 7)) << 4));
        CP_ASYNC16(s + dst, base + (size_t)row * ld + col + ch * 8);
    }
}

// Compute 4 k16-steps. Warp covers MI*16 (M) x NP*16 (N).
template<int MI, int NP>
__device__ __forceinline__ void compute_stage_t(
    unsigned sA, unsigned sB, int lane, int mrow0, int nrow0,
    float (&acc)[MI][2 * NP][4])
{
#pragma unroll
    for (int s = 0; s < 4; ++s) {
        const int ch = s * 2 + (lane >> 4);
        unsigned a[MI][4], rb[NP][4];
#pragma unroll
        for (int mi = 0; mi < MI; ++mi) {
            int row = mrow0 + mi * 16 + (lane & 15);
            unsigned addr = sA + row * 128 + ((ch ^ (row & 7)) << 4);
            LDSM_X4(a[mi][0], a[mi][1], a[mi][2], a[mi][3], addr);
        }
#pragma unroll
        for (int p = 0; p < NP; ++p) {
            int row = nrow0 + p * 16 + (lane & 15);
            unsigned addr = sB + row * 128 + ((ch ^ (row & 7)) << 4);
            LDSM_X4(rb[p][0], rb[p][1], rb[p][2], rb[p][3], addr);
        }
#pragma unroll
        for (int mi = 0; mi < MI; ++mi)
#pragma unroll
            for (int p = 0; p < NP; ++p) {
                MMA16816(acc[mi][2 * p],     a[mi], rb[p][0], rb[p][2]);
                MMA16816(acc[mi][2 * p + 1], a[mi], rb[p][1], rb[p][3]);
            }
    }
}

// ---------------------------------------------------------------------------
// GEMM 1: h = relu(hs @ W^T + b), re-split -> g_h2 [8192, 512]
// CTA tile 64(M) x 128(N); warp grid 2x4 (warp tile 32x32); 256 CTAs.
// K=1024, K_eff=2048, 32 chunks.
// ---------------------------------------------------------------------------
__global__ __launch_bounds__(256, 2) void gemm1_kernel(const float* __restrict__ bias)
{
    extern __shared__ char smem[];
    const unsigned sm = smem_u32(smem);
    const int t = threadIdx.x, lane = t & 31, wid = t >> 5;
    const int wm = wid >> 2, wn = wid & 3;
    const int row0 = blockIdx.y * 64;
    const int col0 = blockIdx.x * 128;

    float acc[2][4][4];
#pragma unroll
    for (int i = 0; i < 2; ++i)
#pragma unroll
        for (int j = 0; j < 4; ++j)
#pragma unroll
            for (int k = 0; k < 4; ++k) acc[i][j][k] = 0.f;

    const __half* A0 = g_hs2 + (size_t)row0 * 2048;
    const __half* B0 = g_w2 + (size_t)col0 * 1024;
    const int K = 1024, nchunks = 32;

    unsigned bufA[3], bufB[3];
#pragma unroll
    for (int s = 0; s < 3; ++s) {
        bufA[s] = sm + s * G1_STAGE;
        bufB[s] = sm + s * G1_STAGE + 8192;
    }

    load_op<64>(A0, 2048, 0, bufA[0], t);
    load_op<128>(B0, 1024, bcol_of(0, K), bufB[0], t);
    CP_COMMIT();
    load_op<64>(A0, 2048, 64, bufA[1], t);
    load_op<128>(B0, 1024, bcol_of(1, K), bufB[1], t);
    CP_COMMIT();

    for (int c = 0; c < nchunks; ++c) {
        if (c + 1 < nchunks) CP_WAIT1(); else CP_WAIT0();
        __syncthreads();
        const int p = c + 2;
        if (p < nchunks) {
            load_op<64>(A0, 2048, p * 64, bufA[p % 3], t);
            load_op<128>(B0, 1024, bcol_of(p, K), bufB[p % 3], t);
            CP_COMMIT();
        }
        compute_stage_t<2, 2>(bufA[c % 3], bufB[c % 3], lane,
                              wm * 32, wn * 32, acc);
    }

    const int rb0 = row0 + wm * 32 + (lane >> 2);
    const int cb0 = col0 + wn * 32 + (lane & 3) * 2;
#pragma unroll
    for (int mi = 0; mi < 2; ++mi) {
#pragma unroll
        for (int ni = 0; ni < 4; ++ni) {
            const int c = cb0 + ni * 8;
            const float b0 = bias[c], b1 = bias[c + 1];
#pragma unroll
            for (int half = 0; half < 2; ++half) {
                const int r = rb0 + mi * 16 + half * 8;
                float v0 = fmaxf(acc[mi][ni][2 * half]     + b0, 0.f);
                float v1 = fmaxf(acc[mi][ni][2 * half + 1] + b1, 0.f);
                __half h0 = __float2half_rn(v0);
                __half h1 = __float2half_rn(v1);
                __half l0 = __float2half_rn(v0 - __half2float(h0));
                __half l1 = __float2half_rn(v1 - __half2float(h1));
                __half* rowp = g_h2 + (size_t)r * 512 + c;
                *reinterpret_cast<__half2*>(rowp)       = __halves2half2(h0, h1);
                *reinterpret_cast<__half2*>(rowp + 256) = __halves2half2(l0, l1);
            }
        }
    }
}

// ---------------------------------------------------------------------------
// GEMM 2: out[b,i,j] = (h_i . h_j) * cw + cb, symmetric — upper-tri tiles only.
// CTA tile 128x128; warp grid 4x2 (warp tile 32x64). 2 CTAs/SM.
// K=256, K_eff=512, 8 chunks. A reads [0,512), B reads hi half [0,256).
// ---------------------------------------------------------------------------
__global__ __launch_bounds__(256, 2) void gemm2_kernel(
    const float* __restrict__ clf_w, const float* __restrict__ clf_b,
    float* __restrict__ out)
{
    extern __shared__ char smem[];
    const unsigned sm = smem_u32(smem);
    const int t = threadIdx.x, lane = t & 31, wid = t >> 5;
    const int wm = wid >> 1, wn = wid & 1;
    const int b = blockIdx.z;

    // Map linear tile index -> (ti, tj) with ti <= tj over a 16x16 tile grid
    int ti = 0, rem = blockIdx.x;
    while (rem >= 16 - ti) { rem -= 16 - ti; ++ti; }
    const int tj = ti + rem;
    const int row0 = ti * 128;
    const int col0 = tj * 128;

    float acc[2][8][4];
#pragma unroll
    for (int i = 0; i < 2; ++i)
#pragma unroll
        for (int j = 0; j < 8; ++j)
#pragma unroll
            for (int k = 0; k < 4; ++k) acc[i][j][k] = 0.f;

    const __half* hb = g_h2 + (size_t)b * SEQ * 512;
    const __half* A0 = hb + (size_t)row0 * 512;
    const __half* B0 = hb + (size_t)col0 * 512;
    const int K = 256, nchunks = 8;

    unsigned bufA[3], bufB[3];
#pragma unroll
    for (int s = 0; s < 3; ++s) {
        bufA[s] = sm + s * G2_STAGE;
        bufB[s] = sm + s * G2_STAGE + 16384;
    }

    load_op<128>(A0, 512, 0, bufA[0], t);
    load_op<128>(B0, 512, bcol_of(0, K), bufB[0], t);
    CP_COMMIT();
    load_op<128>(A0, 512, 64, bufA[1], t);
    load_op<128>(B0, 512, bcol_of(1, K), bufB[1], t);
    CP_COMMIT();

    for (int c = 0; c < nchunks; ++c) {
        if (c + 1 < nchunks) CP_WAIT1(); else CP_WAIT0();
        __syncthreads();
        const int p = c + 2;
        if (p < nchunks) {
            load_op<128>(A0, 512, p * 64, bufA[p % 3], t);
            load_op<128>(B0, 512, bcol_of(p, K), bufB[p % 3], t);
            CP_COMMIT();
        }
        compute_stage_t<2, 4>(bufA[c % 3], bufB[c % 3], lane,
                              wm * 32, wn * 64, acc);
    }
    __syncthreads();   // smem safe for epilogue reuse

    const float cw = __ldg(clf_w);
    const float cb = __ldg(clf_b);
    float* __restrict__ ob = out + (size_t)b * SEQ * SEQ;

    float* tileT = reinterpret_cast<float*>(smem);   // [128][132] transposed stage
    const bool diag = (ti == tj);

    const int rloc = wm * 32 + (lane >> 2);
    const int cloc = wn * 64 + (lane & 3) * 2;
#pragma unroll
    for (int mi = 0; mi < 2; ++mi) {
#pragma unroll
        for (int ni = 0; ni < 8; ++ni) {
            const int c = cloc + ni * 8;
#pragma unroll
            for (int half = 0; half < 2; ++half) {
                const int r = rloc + mi * 16 + half * 8;
                float2 v;
                v.x = acc[mi][ni][2 * half]     * cw + cb;
                v.y = acc[mi][ni][2 * half + 1] * cw + cb;
                *reinterpret_cast<float2*>(
                    ob + (size_t)(row0 + r) * SEQ + col0 + c) = v;
                if (!diag) {
                    tileT[(c)     * 132 + r] = v.x;
                    tileT[(c + 1) * 132 + r] = v.y;
                }
            }
        }
    }

    if (!diag) {
        __syncthreads();
        for (int i = t; i < 128 * 32; i += 256) {
            const int row = i >> 5, q = (i & 31) * 4;
            float4 v = *reinterpret_cast<const float4*>(&tileT[row * 132 + q]);
            *reinterpret_cast<float4*>(
                ob + (size_t)(col0 + row) * SEQ + row0 + q) = v;
        }
    }
}

// ---------------------------------------------------------------------------
extern "C" void kernel_launch(void* const* d_in, const int* in_sizes, int n_in,
                              void* d_out, int out_size)
{
    const float* hs     = (const float*)d_in[0];  // [4, 2048, 1024]
    const float* proj_w = (const float*)d_in[1];  // [256, 1024]
    const float* proj_b = (const float*)d_in[2];  // [256]
    const float* clf_w  = (const float*)d_in[3];  // [1, 1]
    const float* clf_b  = (const float*)d_in[4];  // [1]
    float* out = (float*)d_out;                   // [4, 2048, 2048]

    cudaFuncSetAttribute(gemm1_kernel,
                         cudaFuncAttributeMaxDynamicSharedMemorySize, G1_SMEM);
    cudaFuncSetAttribute(gemm2_kernel,
                         cudaFuncAttributeMaxDynamicSharedMemorySize, G2_SMEM);

    {   // combined split: hs (2M float4) + W (64K float4)
        int n4_hs = 8192 * 1024 / 4;
        int n4_w  = 256 * 1024 / 4;
        int total = n4_hs + n4_w;
        split_kernel<<<(total + 255) / 256, 256>>>(hs, proj_w, n4_hs, n4_w);
    }
    {   // GEMM1: 2 x 128 tiles of 64x128
        dim3 grid(2, 128);
        gemm1_kernel<<<grid, 256, G1_SMEM>>>(proj_b);
    }
    {   // GEMM2: 136 upper-tri tiles x 4 batches
        dim3 grid(136, 1, BATCH);
        gemm2_kernel<<<grid, 256, G2_SMEM>>>(clf_w, clf_b, out);
    }
}